// round 13
// baseline (speedup 1.0000x reference)
#include <cuda_runtime.h>
#include <cuda_bf16.h>
#include <cstdint>

#define NN    100000
#define RR    7
#define DD    64
#define EDIM  16
#define KLIN  448              // R*D (W_lin inner dim)

typedef unsigned long long ull;

// Scratch
__device__ float g_XW[(size_t)NN * RR * DD];   // 179.2 MB: XW[n][r][dout] = x[n] . A_r[:,dout]
__device__ float g_acc[(size_t)NN * DD];       // 25.6 MB: edge-aggregated, L2-resident atomics
// Pre-duplicated f32x2 weights for the XW GEMM:
//   g_WA2[(((r*16+kk)*32+cg)*8 + s*4 + j)] = dup( W_lin[2cg+s][r*64 + 4kk+j] )
__device__ ull  g_WA2[RR * 16 * 32 * 8];       // 229 KB (32 KB per r-slice -> L1-hot)
//   g_WS2[((kk*32+cg)*8 + s*4 + j)] = dup( W_self[2cg+s][4kk+j] )
__device__ ull  g_WS2[16 * 32 * 8];            // 32 KB
// Edge-path weights pushed through W_lin:
//   g_WB[r][j][dout] = sum_din W_edge[din][j] * W_lin[dout][r*64+din]
__device__ float g_WB[RR * EDIM * DD];         // 28 KB
//   g_c[r][dout]    = sum_din b_edge[din]    * W_lin[dout][r*64+din]
__device__ float g_c[RR * DD];                 // 1.75 KB
__device__ float g_bias[DD];                   // b_lin + b_self

// ---- f32x2 helpers (sm_103a packed FMA) -----------------------------------
__device__ __forceinline__ ull f2fma(ull a, ull b, ull c) {
    ull d; asm("fma.rn.f32x2 %0, %1, %2, %3;" : "=l"(d) : "l"(a), "l"(b), "l"(c)); return d;
}
__device__ __forceinline__ float2 up2(ull v) {
    float2 r; asm("mov.b64 {%0, %1}, %2;" : "=f"(r.x), "=f"(r.y) : "l"(v)); return r;
}
__device__ __forceinline__ ull dup2(float v) {
    float2 t = make_float2(v, v);
    return *reinterpret_cast<ull*>(&t);
}

// ---------------------------------------------------------------------------
// K0: build all derived weights
// ---------------------------------------------------------------------------
__global__ void prep_kernel(const float* __restrict__ W_lin,  const float* __restrict__ b_lin,
                            const float* __restrict__ W_self, const float* __restrict__ b_self,
                            const float* __restrict__ W_edge, const float* __restrict__ b_edge) {
    int tid    = blockIdx.x * blockDim.x + threadIdx.x;
    int stride = gridDim.x * blockDim.x;

    // WA2: 7*16*32*8 = 28672 entries
    for (int idx = tid; idx < RR * 16 * 32 * 8; idx += stride) {
        int j  = idx & 3;
        int s  = (idx >> 2) & 1;
        int cg = (idx >> 3) & 31;
        int kk = (idx >> 8) & 15;
        int r  = idx >> 12;
        int col = 2 * cg + s;          // dout
        int k   = 4 * kk + j;          // din
        g_WA2[idx] = dup2(W_lin[col * KLIN + r * DD + k]);
    }
    // WS2: 4096 entries
    for (int idx = tid; idx < 16 * 32 * 8; idx += stride) {
        int j  = idx & 3;
        int s  = (idx >> 2) & 1;
        int cg = (idx >> 3) & 31;
        int kk = idx >> 8;
        int col = 2 * cg + s;
        int k   = 4 * kk + j;
        g_WS2[idx] = dup2(W_self[col * DD + k]);
    }
    // WB: 7*16*64 entries, 64-MAC dot each
    for (int idx = tid; idx < RR * EDIM * DD; idx += stride) {
        int dout = idx & 63;
        int j    = (idx >> 6) & 15;
        int r    = idx >> 10;
        float s = 0.f;
#pragma unroll 8
        for (int din = 0; din < DD; din++)
            s += W_edge[din * EDIM + j] * W_lin[dout * KLIN + r * DD + din];
        g_WB[idx] = s;
    }
    // c: 7*64 entries
    for (int idx = tid; idx < RR * DD; idx += stride) {
        int dout = idx & 63;
        int r    = idx >> 6;
        float s = 0.f;
#pragma unroll 8
        for (int din = 0; din < DD; din++)
            s += b_edge[din] * W_lin[dout * KLIN + r * DD + din];
        g_c[idx] = s;
    }
    if (tid < DD) g_bias[tid] = b_lin[tid] + b_self[tid];
}

// ---------------------------------------------------------------------------
// K1: zero the (small) accumulator
// ---------------------------------------------------------------------------
__global__ void zero_kernel() {
    int idx = blockIdx.x * blockDim.x + threadIdx.x;
    int n4  = NN * DD / 4;
    if (idx < n4) reinterpret_cast<float4*>(g_acc)[idx] = make_float4(0.f, 0.f, 0.f, 0.f);
}

// ---------------------------------------------------------------------------
// K2: XW GEMM — XW[n, r, dout] = sum_k x[n,k] * W_lin[dout, r*64+k]
//     Grid (3125, 7). Block 128 thr, 32 nodes = 16 pairs (p, p+16), 8 KB smem.
//     Thread (cg = t&31, g = t>>5): cols {2cg,2cg+1} of r-slice x pairs {4g..4g+3}.
//     Weights pre-duplicated (no pk2 MOVs); LDS.128 broadcast inputs.
// ---------------------------------------------------------------------------
__global__ __launch_bounds__(128) void xw_kernel(const float* __restrict__ x, int Nn) {
    __shared__ __align__(16) ull u2[16 * 64];   // 16 pairs x 64 k, 8 KB
    int tid  = threadIdx.x;
    int base = blockIdx.x * 32;
    int r    = blockIdx.y;

    // stage x rows, packed (node p, node p+16)
#pragma unroll
    for (int it = 0; it < 8; it++) {
        int idx = it * 128 + tid;
        int p   = idx >> 6;
        int k   = idx & 63;
        int na  = base + p, nb = na + 16;
        float a = (na < Nn) ? x[(size_t)na * DD + k] : 0.f;
        float b = (nb < Nn) ? x[(size_t)nb * DD + k] : 0.f;
        float2 v = make_float2(a, b);
        u2[idx] = *reinterpret_cast<ull*>(&v);
    }
    __syncthreads();

    int cg = tid & 31;
    int g  = tid >> 5;

    ull acc[4][2];
#pragma unroll
    for (int q = 0; q < 4; q++) { acc[q][0] = 0ull; acc[q][1] = 0ull; }

    const ull* wbase = g_WA2 + ((size_t)r * 16) * 32 * 8;
#pragma unroll 2
    for (int kk = 0; kk < 16; kk++) {
        const ulonglong2* wrow = reinterpret_cast<const ulonglong2*>(wbase + (kk * 32 + cg) * 8);
        ulonglong2 wa0 = __ldg(wrow);       // col 2cg  : k 4kk+0, 4kk+1
        ulonglong2 wa1 = __ldg(wrow + 1);   //            k 4kk+2, 4kk+3
        ulonglong2 wb0 = __ldg(wrow + 2);   // col 2cg+1
        ulonglong2 wb1 = __ldg(wrow + 3);
#pragma unroll
        for (int q = 0; q < 4; q++) {
            const ulonglong2* up =
                reinterpret_cast<const ulonglong2*>(&u2[(g * 4 + q) * 64 + 4 * kk]);
            ulonglong2 p0 = up[0];
            ulonglong2 p1 = up[1];
            acc[q][0] = f2fma(wa0.x, p0.x, acc[q][0]);
            acc[q][1] = f2fma(wb0.x, p0.x, acc[q][1]);
            acc[q][0] = f2fma(wa0.y, p0.y, acc[q][0]);
            acc[q][1] = f2fma(wb0.y, p0.y, acc[q][1]);
            acc[q][0] = f2fma(wa1.x, p1.x, acc[q][0]);
            acc[q][1] = f2fma(wb1.x, p1.x, acc[q][1]);
            acc[q][0] = f2fma(wa1.y, p1.y, acc[q][0]);
            acc[q][1] = f2fma(wb1.y, p1.y, acc[q][1]);
        }
    }

    // store: XW[n*448 + r*64 + col]
#pragma unroll
    for (int q = 0; q < 4; q++) {
        float2 a0 = up2(acc[q][0]);   // col 2cg:   (node p, node p+16)
        float2 a1 = up2(acc[q][1]);   // col 2cg+1
        int p  = g * 4 + q;
        int n0 = base + p;
        int n1 = n0 + 16;
        if (n0 < Nn) {
            float2 o = make_float2(a0.x, a1.x);
            *reinterpret_cast<float2*>(g_XW + (size_t)n0 * KLIN + r * DD + 2 * cg) = o;
        }
        if (n1 < Nn) {
            float2 o = make_float2(a0.y, a1.y);
            *reinterpret_cast<float2*>(g_XW + (size_t)n1 * KLIN + r * DD + 2 * cg) = o;
        }
    }
}

// ---------------------------------------------------------------------------
// K3: edge scatter. 16 threads/edge, thread t owns douts [4t, 4t+4).
//     val = w_e * ( XW[ni, rel, :] + ef . B_rel + c_rel )  -> RED.128 into g_acc[no]
//     g_acc is 25.6 MB => L2-resident atomics.
// ---------------------------------------------------------------------------
__global__ __launch_bounds__(256) void edge_kernel(
        const int*   __restrict__ edge_list,
        const float* __restrict__ ew,
        const float* __restrict__ ef,
        int E) {
    __shared__ float4 WB_sh[RR * EDIM * 16];   // [r][j][t] float4 = 28 KB
    __shared__ float4 c_sh[RR * 16];           // [r][t] float4 = 1.75 KB

    int tid = threadIdx.x;
    for (int i = tid; i < RR * EDIM * 16; i += 256)
        WB_sh[i] = reinterpret_cast<const float4*>(g_WB)[i];
    for (int i = tid; i < RR * 16; i += 256)
        c_sh[i] = reinterpret_cast<const float4*>(g_c)[i];
    __syncthreads();

    int e = blockIdx.x * 16 + (tid >> 4);
    int t = tid & 15;
    if (e >= E) return;

    int ni  = edge_list[3 * e + 0];
    int no  = edge_list[3 * e + 1];
    int rel = edge_list[3 * e + 2];
    float w = ew[e];

    // gather transformed source contribution (coalesced 256 B per edge)
    float4 xw = __ldg(reinterpret_cast<const float4*>(
        g_XW + (size_t)ni * KLIN + rel * DD + 4 * t));

    // edge-feature term: ef(16) @ B_rel(16x64), douts 4t..4t+3
    float4 acc = c_sh[rel * 16 + t];
    const float4* efv = reinterpret_cast<const float4*>(ef + (size_t)e * EDIM);
#pragma unroll
    for (int gq = 0; gq < 4; gq++) {
        float4 fg = efv[gq];
        float vals[4] = {fg.x, fg.y, fg.z, fg.w};
#pragma unroll
        for (int s = 0; s < 4; s++) {
            float4 bv = WB_sh[(rel * EDIM + 4 * gq + s) * 16 + t];
            float  fj = vals[s];
            acc.x += bv.x * fj;
            acc.y += bv.y * fj;
            acc.z += bv.z * fj;
            acc.w += bv.w * fj;
        }
    }

    float4 val;
    val.x = w * (xw.x + acc.x);
    val.y = w * (xw.y + acc.y);
    val.z = w * (xw.z + acc.z);
    val.w = w * (xw.w + acc.w);

    float4* dst = reinterpret_cast<float4*>(g_acc + (size_t)no * DD + 4 * t);
    atomicAdd(dst, val);
}

// ---------------------------------------------------------------------------
// K4: epilogue — out[n] = relu( g_acc[n] + x[n] @ W_self^T + bias )
//     Same GEMM structure as xw_kernel, single 64-col slice (K=64).
// ---------------------------------------------------------------------------
__global__ __launch_bounds__(128) void out2_kernel(const float* __restrict__ x,
                                                   float* __restrict__ out, int Nn) {
    __shared__ __align__(16) ull u2[16 * 64];   // 8 KB
    int tid  = threadIdx.x;
    int base = blockIdx.x * 32;

#pragma unroll
    for (int it = 0; it < 8; it++) {
        int idx = it * 128 + tid;
        int p   = idx >> 6;
        int k   = idx & 63;
        int na  = base + p, nb = na + 16;
        float a = (na < Nn) ? x[(size_t)na * DD + k] : 0.f;
        float b = (nb < Nn) ? x[(size_t)nb * DD + k] : 0.f;
        float2 v = make_float2(a, b);
        u2[idx] = *reinterpret_cast<ull*>(&v);
    }
    __syncthreads();

    int cg = tid & 31;
    int g  = tid >> 5;

    ull acc[4][2];
#pragma unroll
    for (int q = 0; q < 4; q++) { acc[q][0] = 0ull; acc[q][1] = 0ull; }

#pragma unroll 2
    for (int kk = 0; kk < 16; kk++) {
        const ulonglong2* wrow = reinterpret_cast<const ulonglong2*>(g_WS2 + (kk * 32 + cg) * 8);
        ulonglong2 wa0 = __ldg(wrow);
        ulonglong2 wa1 = __ldg(wrow + 1);
        ulonglong2 wb0 = __ldg(wrow + 2);
        ulonglong2 wb1 = __ldg(wrow + 3);
#pragma unroll
        for (int q = 0; q < 4; q++) {
            const ulonglong2* up =
                reinterpret_cast<const ulonglong2*>(&u2[(g * 4 + q) * 64 + 4 * kk]);
            ulonglong2 p0 = up[0];
            ulonglong2 p1 = up[1];
            acc[q][0] = f2fma(wa0.x, p0.x, acc[q][0]);
            acc[q][1] = f2fma(wb0.x, p0.x, acc[q][1]);
            acc[q][0] = f2fma(wa0.y, p0.y, acc[q][0]);
            acc[q][1] = f2fma(wb0.y, p0.y, acc[q][1]);
            acc[q][0] = f2fma(wa1.x, p1.x, acc[q][0]);
            acc[q][1] = f2fma(wb1.x, p1.x, acc[q][1]);
            acc[q][0] = f2fma(wa1.y, p1.y, acc[q][0]);
            acc[q][1] = f2fma(wb1.y, p1.y, acc[q][1]);
        }
    }

    float bc0 = g_bias[2 * cg];
    float bc1 = g_bias[2 * cg + 1];
#pragma unroll
    for (int q = 0; q < 4; q++) {
        float2 a0 = up2(acc[q][0]);
        float2 a1 = up2(acc[q][1]);
        int p  = g * 4 + q;
        int n0 = base + p;
        int n1 = n0 + 16;
        if (n0 < Nn) {
            float2 av = *reinterpret_cast<const float2*>(g_acc + (size_t)n0 * DD + 2 * cg);
            float2 o  = make_float2(fmaxf(a0.x + av.x + bc0, 0.f),
                                    fmaxf(a1.x + av.y + bc1, 0.f));
            *reinterpret_cast<float2*>(out + (size_t)n0 * DD + 2 * cg) = o;
        }
        if (n1 < Nn) {
            float2 av = *reinterpret_cast<const float2*>(g_acc + (size_t)n1 * DD + 2 * cg);
            float2 o  = make_float2(fmaxf(a0.y + av.x + bc0, 0.f),
                                    fmaxf(a1.y + av.y + bc1, 0.f));
            *reinterpret_cast<float2*>(out + (size_t)n1 * DD + 2 * cg) = o;
        }
    }
}

// ---------------------------------------------------------------------------
extern "C" void kernel_launch(void* const* d_in, const int* in_sizes, int n_in,
                              void* d_out, int out_size) {
    const float* x      = (const float*)d_in[0];
    const int*   elist  = (const int*)  d_in[1];
    const float* ew     = (const float*)d_in[2];
    const float* ef     = (const float*)d_in[3];
    const float* W_lin  = (const float*)d_in[4];
    const float* b_lin  = (const float*)d_in[5];
    const float* W_self = (const float*)d_in[6];
    const float* b_self = (const float*)d_in[7];
    const float* W_edge = (const float*)d_in[8];
    const float* b_edge = (const float*)d_in[9];
    float*       out    = (float*)d_out;

    int E = in_sizes[2];            // edge_weight element count
    int N = in_sizes[0] / DD;       // x element count / D

    prep_kernel<<<128, 256>>>(W_lin, b_lin, W_self, b_self, W_edge, b_edge);

    zero_kernel<<<(NN * DD / 4 + 255) / 256, 256>>>();

    {
        dim3 grid((N + 31) / 32, RR);
        xw_kernel<<<grid, 128>>>(x, N);
    }

    edge_kernel<<<(E + 15) / 16, 256>>>(elist, ew, ef, E);

    out2_kernel<<<(N + 31) / 32, 128>>>(x, out, N);
}

// round 14
// speedup vs baseline: 1.7487x; 1.7487x over previous
#include <cuda_runtime.h>
#include <cuda_bf16.h>
#include <cstdint>

#define NN    100000
#define RR    7
#define DD    64
#define EDIM  16
#define KLIN  448              // R*D
#define KEPI  192              // 112 (F) + 16 (s + pad) + 64 (x)

typedef unsigned long long ull;

// Scratch
__device__ float g_XW[(size_t)NN * RR * DD];   // 179.2 MB: XW[n][r][c] = x[n] . W_lin[c][r*64:...]
__device__ float g_acc[(size_t)NN * DD];       // 25.6 MB (L2-resident atomics)
__device__ float g_F[(size_t)NN * RR * EDIM];  // 44.8 MB: F[n][r][j] = sum w_e ef[e][j]
__device__ float g_s[NN * RR];                 // 2.8 MB:  s[n][r]   = sum w_e
// xw weights, chunk-coalesced + f32x2-dup'd:
//   flat ull idx = (((r*16+kk)*4 + ch)*32 + cg)*2 + j ; col=2cg+(ch>>1), k=4kk+(ch&1)*2+j
__device__ ull g_WA2[RR * 16 * 4 * 32 * 2];    // 229 KB
// epilogue weights (K=192), same chunked layout:
//   flat ull idx = ((kk*4 + ch)*32 + cg)*2 + j ; col=2cg+(ch>>1), k=4kk+(ch&1)*2+j
__device__ ull g_WE2[48 * 4 * 32 * 2];         // 98 KB
__device__ float g_bias[DD];                   // b_lin + b_self

// ---- f32x2 helpers --------------------------------------------------------
__device__ __forceinline__ ull f2fma(ull a, ull b, ull c) {
    ull d; asm("fma.rn.f32x2 %0, %1, %2, %3;" : "=l"(d) : "l"(a), "l"(b), "l"(c)); return d;
}
__device__ __forceinline__ float2 up2(ull v) {
    float2 r; asm("mov.b64 {%0, %1}, %2;" : "=f"(r.x), "=f"(r.y) : "l"(v)); return r;
}
__device__ __forceinline__ ull dup2(float v) {
    float2 t = make_float2(v, v);
    return *reinterpret_cast<ull*>(&t);
}

// ---------------------------------------------------------------------------
// K0: build derived weights
// ---------------------------------------------------------------------------
__global__ void prep_kernel(const float* __restrict__ W_lin,  const float* __restrict__ b_lin,
                            const float* __restrict__ W_self, const float* __restrict__ b_self,
                            const float* __restrict__ W_edge, const float* __restrict__ b_edge) {
    int tid    = blockIdx.x * blockDim.x + threadIdx.x;
    int stride = gridDim.x * blockDim.x;

    // WA2: 28672 ull entries = dup( W_lin[col][r*64 + k] )
    for (int idx = tid; idx < RR * 16 * 4 * 32 * 2; idx += stride) {
        int j  = idx & 1;
        int cg = (idx >> 1) & 31;
        int ch = (idx >> 6) & 3;
        int kk = (idx >> 8) & 15;
        int r  = idx >> 12;
        int col = 2 * cg + (ch >> 1);
        int k   = 4 * kk + (ch & 1) * 2 + j;
        g_WA2[idx] = dup2(W_lin[col * KLIN + r * DD + k]);
    }

    // WE2: 12288 ull entries; logical Wfull[col][k], k in [0,192)
    for (int idx = tid; idx < 48 * 4 * 32 * 2; idx += stride) {
        int j  = idx & 1;
        int cg = (idx >> 1) & 31;
        int ch = (idx >> 6) & 3;
        int kk = idx >> 8;
        int col = 2 * cg + (ch >> 1);
        int k   = 4 * kk + (ch & 1) * 2 + j;
        float v;
        if (k < 112) {              // B_r[j][col] = sum_din W_edge[din][jj] * W_lin[col][r*64+din]
            int r  = k >> 4;
            int jj = k & 15;
            float s = 0.f;
#pragma unroll 8
            for (int din = 0; din < DD; din++)
                s += W_edge[din * EDIM + jj] * W_lin[col * KLIN + r * DD + din];
            v = s;
        } else if (k < 119) {       // c_r[col] = sum_din b_edge[din] * W_lin[col][r*64+din]
            int r = k - 112;
            float s = 0.f;
#pragma unroll 8
            for (int din = 0; din < DD; din++)
                s += b_edge[din] * W_lin[col * KLIN + r * DD + din];
            v = s;
        } else if (k < 128) {
            v = 0.f;                // padding
        } else {
            v = W_self[col * DD + (k - 128)];
        }
        g_WE2[idx] = dup2(v);
    }

    if (tid < DD) g_bias[tid] = b_lin[tid] + b_self[tid];
}

// ---------------------------------------------------------------------------
// K1: zero g_acc + g_F + g_s (73 MB total)
// ---------------------------------------------------------------------------
__global__ void zero_kernel() {
    const int n_acc = NN * DD / 4;          // 1.6M float4
    const int n_F   = NN * RR * EDIM / 4;   // 2.8M float4
    const int n_s   = NN * RR / 4;          // 175K float4
    int i = blockIdx.x * blockDim.x + threadIdx.x;
    float4 z = make_float4(0.f, 0.f, 0.f, 0.f);
    if (i < n_acc) { reinterpret_cast<float4*>(g_acc)[i] = z; return; }
    i -= n_acc;
    if (i < n_F)   { reinterpret_cast<float4*>(g_F)[i] = z; return; }
    i -= n_F;
    if (i < n_s)   { reinterpret_cast<float4*>(g_s)[i] = z; }
}

// ---------------------------------------------------------------------------
// K2: XW GEMM — XW[n, r, c] = sum_k x[n,k] * W_lin[c, r*64+k]
//     Grid (3125, 7), 128 thr, 32 nodes = 16 pairs. Chunk-coalesced weights.
// ---------------------------------------------------------------------------
__global__ __launch_bounds__(128) void xw_kernel(const float* __restrict__ x, int Nn) {
    __shared__ __align__(16) ull u2[16 * 64];   // 8 KB
    int tid  = threadIdx.x;
    int base = blockIdx.x * 32;
    int r    = blockIdx.y;

#pragma unroll
    for (int it = 0; it < 8; it++) {
        int idx = it * 128 + tid;
        int p   = idx >> 6;
        int k   = idx & 63;
        int na  = base + p, nb = na + 16;
        float a = (na < Nn) ? x[(size_t)na * DD + k] : 0.f;
        float b = (nb < Nn) ? x[(size_t)nb * DD + k] : 0.f;
        float2 v = make_float2(a, b);
        u2[idx] = *reinterpret_cast<ull*>(&v);
    }
    __syncthreads();

    int cg = tid & 31;
    int g  = tid >> 5;

    ull acc[4][2];
#pragma unroll
    for (int q = 0; q < 4; q++) { acc[q][0] = 0ull; acc[q][1] = 0ull; }

    const ulonglong2* wbase = reinterpret_cast<const ulonglong2*>(g_WA2) + (size_t)r * 16 * 4 * 32;
#pragma unroll 2
    for (int kk = 0; kk < 16; kk++) {
        const ulonglong2* wr = wbase + kk * 128 + cg;     // each LDG.128 coalesced (512B/warp)
        ulonglong2 wa0 = __ldg(wr);          // col 2cg,   k 4kk+0,1
        ulonglong2 wa1 = __ldg(wr + 32);     // col 2cg,   k 4kk+2,3
        ulonglong2 wb0 = __ldg(wr + 64);     // col 2cg+1, k 4kk+0,1
        ulonglong2 wb1 = __ldg(wr + 96);     // col 2cg+1, k 4kk+2,3
#pragma unroll
        for (int q = 0; q < 4; q++) {
            const ulonglong2* up =
                reinterpret_cast<const ulonglong2*>(&u2[(g * 4 + q) * 64 + 4 * kk]);
            ulonglong2 p0 = up[0];
            ulonglong2 p1 = up[1];
            acc[q][0] = f2fma(wa0.x, p0.x, acc[q][0]);
            acc[q][1] = f2fma(wb0.x, p0.x, acc[q][1]);
            acc[q][0] = f2fma(wa0.y, p0.y, acc[q][0]);
            acc[q][1] = f2fma(wb0.y, p0.y, acc[q][1]);
            acc[q][0] = f2fma(wa1.x, p1.x, acc[q][0]);
            acc[q][1] = f2fma(wb1.x, p1.x, acc[q][1]);
            acc[q][0] = f2fma(wa1.y, p1.y, acc[q][0]);
            acc[q][1] = f2fma(wb1.y, p1.y, acc[q][1]);
        }
    }

#pragma unroll
    for (int q = 0; q < 4; q++) {
        float2 a0 = up2(acc[q][0]);
        float2 a1 = up2(acc[q][1]);
        int p  = g * 4 + q;
        int n0 = base + p;
        int n1 = n0 + 16;
        if (n0 < Nn) {
            float2 o = make_float2(a0.x, a1.x);
            *reinterpret_cast<float2*>(g_XW + (size_t)n0 * KLIN + r * DD + 2 * cg) = o;
        }
        if (n1 < Nn) {
            float2 o = make_float2(a0.y, a1.y);
            *reinterpret_cast<float2*>(g_XW + (size_t)n1 * KLIN + r * DD + 2 * cg) = o;
        }
    }
}

// ---------------------------------------------------------------------------
// K3: edge scatter — NO weight reads. 16 threads/edge, thread t owns [4t,4t+4).
//     g_acc[no]        += w * XW[ni, rel]          (16 RED.128, L2)
//     g_F[no,rel]      += w * ef[e]                (4 RED.128, lanes 0-3)
//     g_s[no,rel]      += w                        (1 RED.F32, lane 0)
// ---------------------------------------------------------------------------
__global__ __launch_bounds__(256) void edge_kernel(
        const int*   __restrict__ edge_list,
        const float* __restrict__ ew,
        const float* __restrict__ ef,
        int E) {
    int tid = threadIdx.x;
    int e = blockIdx.x * 16 + (tid >> 4);
    int t = tid & 15;
    if (e >= E) return;

    int ni  = edge_list[3 * e + 0];
    int no  = edge_list[3 * e + 1];
    int rel = edge_list[3 * e + 2];
    float w = ew[e];

    // transformed-source gather (256 B coalesced across the 16 lanes)
    float4 xw = __ldg(reinterpret_cast<const float4*>(
        g_XW + (size_t)ni * KLIN + rel * DD + 4 * t));
    float4 val = make_float4(w * xw.x, w * xw.y, w * xw.z, w * xw.w);
    atomicAdd(reinterpret_cast<float4*>(g_acc + (size_t)no * DD + 4 * t), val);

    if (t < 4) {
        float4 fe = __ldg(reinterpret_cast<const float4*>(ef + (size_t)e * EDIM) + t);
        float4 fv = make_float4(w * fe.x, w * fe.y, w * fe.z, w * fe.w);
        atomicAdd(reinterpret_cast<float4*>(g_F + ((size_t)no * RR + rel) * EDIM + 4 * t), fv);
    }
    if (t == 0) atomicAdd(&g_s[no * RR + rel], w);
}

// ---------------------------------------------------------------------------
// K4: epilogue GEMM (K=192) over [F(112) ‖ s(7)+pad ‖ x(64)]:
//     out[n] = relu( Wfull @ in + g_acc[n] + bias )
//     128 thr, 32 nodes = 16 pairs, 24 KB smem.
// ---------------------------------------------------------------------------
__global__ __launch_bounds__(128) void out2_kernel(const float* __restrict__ x,
                                                   float* __restrict__ out, int Nn) {
    __shared__ __align__(16) ull u2[16 * KEPI];   // 24 KB
    int tid  = threadIdx.x;
    int base = blockIdx.x * 32;

    // stage concatenated inputs, packed (node p, node p+16)
    for (int it = 0; it < 24; it++) {
        int idx = it * 128 + tid;
        int p   = idx / KEPI;
        int k   = idx % KEPI;
        int na  = base + p, nb = na + 16;
        float a = 0.f, b = 0.f;
        if (k < 112) {
            if (na < Nn) a = g_F[(size_t)na * 112 + k];
            if (nb < Nn) b = g_F[(size_t)nb * 112 + k];
        } else if (k < 119) {
            int r = k - 112;
            if (na < Nn) a = g_s[na * RR + r];
            if (nb < Nn) b = g_s[nb * RR + r];
        } else if (k >= 128) {
            int kx = k - 128;
            if (na < Nn) a = x[(size_t)na * DD + kx];
            if (nb < Nn) b = x[(size_t)nb * DD + kx];
        }
        float2 v = make_float2(a, b);
        u2[idx] = *reinterpret_cast<ull*>(&v);
    }
    __syncthreads();

    int cg = tid & 31;
    int g  = tid >> 5;

    ull acc[4][2];
#pragma unroll
    for (int q = 0; q < 4; q++) { acc[q][0] = 0ull; acc[q][1] = 0ull; }

#pragma unroll 2
    for (int kk = 0; kk < 48; kk++) {
        const ulonglong2* wr = reinterpret_cast<const ulonglong2*>(g_WE2) + kk * 128 + cg;
        ulonglong2 wa0 = __ldg(wr);
        ulonglong2 wa1 = __ldg(wr + 32);
        ulonglong2 wb0 = __ldg(wr + 64);
        ulonglong2 wb1 = __ldg(wr + 96);
#pragma unroll
        for (int q = 0; q < 4; q++) {
            const ulonglong2* up =
                reinterpret_cast<const ulonglong2*>(&u2[(g * 4 + q) * KEPI + 4 * kk]);
            ulonglong2 p0 = up[0];
            ulonglong2 p1 = up[1];
            acc[q][0] = f2fma(wa0.x, p0.x, acc[q][0]);
            acc[q][1] = f2fma(wb0.x, p0.x, acc[q][1]);
            acc[q][0] = f2fma(wa0.y, p0.y, acc[q][0]);
            acc[q][1] = f2fma(wb0.y, p0.y, acc[q][1]);
            acc[q][0] = f2fma(wa1.x, p1.x, acc[q][0]);
            acc[q][1] = f2fma(wb1.x, p1.x, acc[q][1]);
            acc[q][0] = f2fma(wa1.y, p1.y, acc[q][0]);
            acc[q][1] = f2fma(wb1.y, p1.y, acc[q][1]);
        }
    }

    float bc0 = g_bias[2 * cg];
    float bc1 = g_bias[2 * cg + 1];
#pragma unroll
    for (int q = 0; q < 4; q++) {
        float2 a0 = up2(acc[q][0]);
        float2 a1 = up2(acc[q][1]);
        int p  = g * 4 + q;
        int n0 = base + p;
        int n1 = n0 + 16;
        if (n0 < Nn) {
            float2 av = *reinterpret_cast<const float2*>(g_acc + (size_t)n0 * DD + 2 * cg);
            float2 o  = make_float2(fmaxf(a0.x + av.x + bc0, 0.f),
                                    fmaxf(a1.x + av.y + bc1, 0.f));
            *reinterpret_cast<float2*>(out + (size_t)n0 * DD + 2 * cg) = o;
        }
        if (n1 < Nn) {
            float2 av = *reinterpret_cast<const float2*>(g_acc + (size_t)n1 * DD + 2 * cg);
            float2 o  = make_float2(fmaxf(a0.y + av.x + bc0, 0.f),
                                    fmaxf(a1.y + av.y + bc1, 0.f));
            *reinterpret_cast<float2*>(out + (size_t)n1 * DD + 2 * cg) = o;
        }
    }
}

// ---------------------------------------------------------------------------
extern "C" void kernel_launch(void* const* d_in, const int* in_sizes, int n_in,
                              void* d_out, int out_size) {
    const float* x      = (const float*)d_in[0];
    const int*   elist  = (const int*)  d_in[1];
    const float* ew     = (const float*)d_in[2];
    const float* ef     = (const float*)d_in[3];
    const float* W_lin  = (const float*)d_in[4];
    const float* b_lin  = (const float*)d_in[5];
    const float* W_self = (const float*)d_in[6];
    const float* b_self = (const float*)d_in[7];
    const float* W_edge = (const float*)d_in[8];
    const float* b_edge = (const float*)d_in[9];
    float*       out    = (float*)d_out;

    int E = in_sizes[2];
    int N = in_sizes[0] / DD;

    prep_kernel<<<128, 256>>>(W_lin, b_lin, W_self, b_self, W_edge, b_edge);

    {
        int total = NN * DD / 4 + NN * RR * EDIM / 4 + NN * RR / 4;
        zero_kernel<<<(total + 255) / 256, 256>>>();
    }

    {
        dim3 grid((N + 31) / 32, RR);
        xw_kernel<<<grid, 128>>>(x, N);
    }

    edge_kernel<<<(E + 15) / 16, 256>>>(elist, ew, ef, E);

    out2_kernel<<<(N + 31) / 32, 128>>>(x, out, N);
}

// round 15
// speedup vs baseline: 1.8198x; 1.0407x over previous
#include <cuda_runtime.h>
#include <cuda_fp16.h>
#include <cstdint>

#define NN    100000
#define RR    7
#define DD    64
#define EDIM  16
#define KLIN  448              // R*D
#define KEPI  192              // 112 (F) + 16 (s + pad) + 64 (x)

typedef unsigned long long ull;

// Scratch
__device__ __half g_XWh[(size_t)NN * RR * DD]; // 89.6 MB (fits L2): XW[n][r][c] in fp16
__device__ float g_acc[(size_t)NN * DD];       // 25.6 MB (L2-resident atomics)
__device__ float g_F[(size_t)NN * RR * EDIM];  // 44.8 MB: F[n][r][j] = sum w_e ef[e][j]
__device__ float g_s[NN * RR];                 // 2.8 MB:  s[n][r]   = sum w_e
// xw weights, chunk-coalesced + f32x2-dup'd:
//   flat ull idx = (((r*16+kk)*4 + ch)*32 + cg)*2 + j ; col=2cg+(ch>>1), k=4kk+(ch&1)*2+j
__device__ ull g_WA2[RR * 16 * 4 * 32 * 2];    // 229 KB
// epilogue weights (K=192), same chunked layout
__device__ ull g_WE2[48 * 4 * 32 * 2];         // 98 KB
__device__ float g_bias[DD];                   // b_lin + b_self

// ---- f32x2 helpers --------------------------------------------------------
__device__ __forceinline__ ull f2fma(ull a, ull b, ull c) {
    ull d; asm("fma.rn.f32x2 %0, %1, %2, %3;" : "=l"(d) : "l"(a), "l"(b), "l"(c)); return d;
}
__device__ __forceinline__ float2 up2(ull v) {
    float2 r; asm("mov.b64 {%0, %1}, %2;" : "=f"(r.x), "=f"(r.y) : "l"(v)); return r;
}
__device__ __forceinline__ ull dup2(float v) {
    float2 t = make_float2(v, v);
    return *reinterpret_cast<ull*>(&t);
}

// ---------------------------------------------------------------------------
// K0: build derived weights
// ---------------------------------------------------------------------------
__global__ void prep_kernel(const float* __restrict__ W_lin,  const float* __restrict__ b_lin,
                            const float* __restrict__ W_self, const float* __restrict__ b_self,
                            const float* __restrict__ W_edge, const float* __restrict__ b_edge) {
    int tid    = blockIdx.x * blockDim.x + threadIdx.x;
    int stride = gridDim.x * blockDim.x;

    // WA2: 28672 ull entries = dup( W_lin[col][r*64 + k] )
    for (int idx = tid; idx < RR * 16 * 4 * 32 * 2; idx += stride) {
        int j  = idx & 1;
        int cg = (idx >> 1) & 31;
        int ch = (idx >> 6) & 3;
        int kk = (idx >> 8) & 15;
        int r  = idx >> 12;
        int col = 2 * cg + (ch >> 1);
        int k   = 4 * kk + (ch & 1) * 2 + j;
        g_WA2[idx] = dup2(W_lin[col * KLIN + r * DD + k]);
    }

    // WE2: 12288 ull entries; logical Wfull[col][k], k in [0,192)
    for (int idx = tid; idx < 48 * 4 * 32 * 2; idx += stride) {
        int j  = idx & 1;
        int cg = (idx >> 1) & 31;
        int ch = (idx >> 6) & 3;
        int kk = idx >> 8;
        int col = 2 * cg + (ch >> 1);
        int k   = 4 * kk + (ch & 1) * 2 + j;
        float v;
        if (k < 112) {              // B_r[j][col]
            int r  = k >> 4;
            int jj = k & 15;
            float s = 0.f;
#pragma unroll 8
            for (int din = 0; din < DD; din++)
                s += W_edge[din * EDIM + jj] * W_lin[col * KLIN + r * DD + din];
            v = s;
        } else if (k < 119) {       // c_r[col]
            int r = k - 112;
            float s = 0.f;
#pragma unroll 8
            for (int din = 0; din < DD; din++)
                s += b_edge[din] * W_lin[col * KLIN + r * DD + din];
            v = s;
        } else if (k < 128) {
            v = 0.f;                // padding
        } else {
            v = W_self[col * DD + (k - 128)];
        }
        g_WE2[idx] = dup2(v);
    }

    if (tid < DD) g_bias[tid] = b_lin[tid] + b_self[tid];
}

// ---------------------------------------------------------------------------
// K1: zero g_acc + g_F + g_s (73 MB total)
// ---------------------------------------------------------------------------
__global__ void zero_kernel() {
    const int n_acc = NN * DD / 4;
    const int n_F   = NN * RR * EDIM / 4;
    const int n_s   = NN * RR / 4;
    int i = blockIdx.x * blockDim.x + threadIdx.x;
    float4 z = make_float4(0.f, 0.f, 0.f, 0.f);
    if (i < n_acc) { reinterpret_cast<float4*>(g_acc)[i] = z; return; }
    i -= n_acc;
    if (i < n_F)   { reinterpret_cast<float4*>(g_F)[i] = z; return; }
    i -= n_F;
    if (i < n_s)   { reinterpret_cast<float4*>(g_s)[i] = z; }
}

// ---------------------------------------------------------------------------
// K2: XW GEMM — XW[n, r, c] = sum_k x[n,k] * W_lin[c, r*64+k], stored fp16.
//     Grid (3125, 7), 128 thr, 32 nodes = 16 pairs. Chunk-coalesced weights.
// ---------------------------------------------------------------------------
__global__ __launch_bounds__(128) void xw_kernel(const float* __restrict__ x, int Nn) {
    __shared__ __align__(16) ull u2[16 * 64];   // 8 KB
    int tid  = threadIdx.x;
    int base = blockIdx.x * 32;
    int r    = blockIdx.y;

#pragma unroll
    for (int it = 0; it < 8; it++) {
        int idx = it * 128 + tid;
        int p   = idx >> 6;
        int k   = idx & 63;
        int na  = base + p, nb = na + 16;
        float a = (na < Nn) ? x[(size_t)na * DD + k] : 0.f;
        float b = (nb < Nn) ? x[(size_t)nb * DD + k] : 0.f;
        float2 v = make_float2(a, b);
        u2[idx] = *reinterpret_cast<ull*>(&v);
    }
    __syncthreads();

    int cg = tid & 31;
    int g  = tid >> 5;

    ull acc[4][2];
#pragma unroll
    for (int q = 0; q < 4; q++) { acc[q][0] = 0ull; acc[q][1] = 0ull; }

    const ulonglong2* wbase = reinterpret_cast<const ulonglong2*>(g_WA2) + (size_t)r * 16 * 4 * 32;
#pragma unroll 2
    for (int kk = 0; kk < 16; kk++) {
        const ulonglong2* wr = wbase + kk * 128 + cg;     // coalesced 512B/warp
        ulonglong2 wa0 = __ldg(wr);          // col 2cg,   k 4kk+0,1
        ulonglong2 wa1 = __ldg(wr + 32);     // col 2cg,   k 4kk+2,3
        ulonglong2 wb0 = __ldg(wr + 64);     // col 2cg+1, k 4kk+0,1
        ulonglong2 wb1 = __ldg(wr + 96);     // col 2cg+1, k 4kk+2,3
#pragma unroll
        for (int q = 0; q < 4; q++) {
            const ulonglong2* up =
                reinterpret_cast<const ulonglong2*>(&u2[(g * 4 + q) * 64 + 4 * kk]);
            ulonglong2 p0 = up[0];
            ulonglong2 p1 = up[1];
            acc[q][0] = f2fma(wa0.x, p0.x, acc[q][0]);
            acc[q][1] = f2fma(wb0.x, p0.x, acc[q][1]);
            acc[q][0] = f2fma(wa0.y, p0.y, acc[q][0]);
            acc[q][1] = f2fma(wb0.y, p0.y, acc[q][1]);
            acc[q][0] = f2fma(wa1.x, p1.x, acc[q][0]);
            acc[q][1] = f2fma(wb1.x, p1.x, acc[q][1]);
            acc[q][0] = f2fma(wa1.y, p1.y, acc[q][0]);
            acc[q][1] = f2fma(wb1.y, p1.y, acc[q][1]);
        }
    }

    // store fp16: cols (2cg, 2cg+1) per node as one __half2 (4 B)
#pragma unroll
    for (int q = 0; q < 4; q++) {
        float2 a0 = up2(acc[q][0]);   // col 2cg:   (node p, node p+16)
        float2 a1 = up2(acc[q][1]);   // col 2cg+1
        int p  = g * 4 + q;
        int n0 = base + p;
        int n1 = n0 + 16;
        if (n0 < Nn) {
            __half2 h = __float22half2_rn(make_float2(a0.x, a1.x));
            *reinterpret_cast<__half2*>(g_XWh + (size_t)n0 * KLIN + r * DD + 2 * cg) = h;
        }
        if (n1 < Nn) {
            __half2 h = __float22half2_rn(make_float2(a0.y, a1.y));
            *reinterpret_cast<__half2*>(g_XWh + (size_t)n1 * KLIN + r * DD + 2 * cg) = h;
        }
    }
}

// ---------------------------------------------------------------------------
// K3: edge scatter — NO weight reads. 16 threads/edge, thread t owns [4t,4t+4).
//     g_acc[no]   += w * XWh[ni, rel]   (gather 128 B fp16, RED.128 fp32)
//     g_F[no,rel] += w * ef[e]          (lanes 0-3)
//     g_s[no,rel] += w                  (lane 0)
// ---------------------------------------------------------------------------
__global__ __launch_bounds__(256) void edge_kernel(
        const int*   __restrict__ edge_list,
        const float* __restrict__ ew,
        const float* __restrict__ ef,
        int E) {
    int tid = threadIdx.x;
    int e = blockIdx.x * 16 + (tid >> 4);
    int t = tid & 15;
    if (e >= E) return;

    int ni  = edge_list[3 * e + 0];
    int no  = edge_list[3 * e + 1];
    int rel = edge_list[3 * e + 2];
    float w = ew[e];

    // fp16 gather: 8 B per lane, 128 B per edge, mostly L2-hit (89.6 MB region)
    uint2 hraw = __ldg(reinterpret_cast<const uint2*>(
        g_XWh + (size_t)ni * KLIN + rel * DD + 4 * t));
    __half2 h0 = *reinterpret_cast<__half2*>(&hraw.x);
    __half2 h1 = *reinterpret_cast<__half2*>(&hraw.y);
    float2 f0 = __half22float2(h0);
    float2 f1 = __half22float2(h1);

    float4 val = make_float4(w * f0.x, w * f0.y, w * f1.x, w * f1.y);
    atomicAdd(reinterpret_cast<float4*>(g_acc + (size_t)no * DD + 4 * t), val);

    if (t < 4) {
        float4 fe = __ldg(reinterpret_cast<const float4*>(ef + (size_t)e * EDIM) + t);
        float4 fv = make_float4(w * fe.x, w * fe.y, w * fe.z, w * fe.w);
        atomicAdd(reinterpret_cast<float4*>(g_F + ((size_t)no * RR + rel) * EDIM + 4 * t), fv);
    }
    if (t == 0) atomicAdd(&g_s[no * RR + rel], w);
}

// ---------------------------------------------------------------------------
// K4: epilogue GEMM (K=192) over [F(112) ‖ s(7)+pad ‖ x(64)]:
//     out[n] = relu( Wfull @ in + g_acc[n] + bias )
// ---------------------------------------------------------------------------
__global__ __launch_bounds__(128) void out2_kernel(const float* __restrict__ x,
                                                   float* __restrict__ out, int Nn) {
    __shared__ __align__(16) ull u2[16 * KEPI];   // 24 KB
    int tid  = threadIdx.x;
    int base = blockIdx.x * 32;

    for (int it = 0; it < 24; it++) {
        int idx = it * 128 + tid;
        int p   = idx / KEPI;
        int k   = idx % KEPI;
        int na  = base + p, nb = na + 16;
        float a = 0.f, b = 0.f;
        if (k < 112) {
            if (na < Nn) a = g_F[(size_t)na * 112 + k];
            if (nb < Nn) b = g_F[(size_t)nb * 112 + k];
        } else if (k < 119) {
            int r = k - 112;
            if (na < Nn) a = g_s[na * RR + r];
            if (nb < Nn) b = g_s[nb * RR + r];
        } else if (k >= 128) {
            int kx = k - 128;
            if (na < Nn) a = x[(size_t)na * DD + kx];
            if (nb < Nn) b = x[(size_t)nb * DD + kx];
        }
        float2 v = make_float2(a, b);
        u2[idx] = *reinterpret_cast<ull*>(&v);
    }
    __syncthreads();

    int cg = tid & 31;
    int g  = tid >> 5;

    ull acc[4][2];
#pragma unroll
    for (int q = 0; q < 4; q++) { acc[q][0] = 0ull; acc[q][1] = 0ull; }

#pragma unroll 2
    for (int kk = 0; kk < 48; kk++) {
        const ulonglong2* wr = reinterpret_cast<const ulonglong2*>(g_WE2) + kk * 128 + cg;
        ulonglong2 wa0 = __ldg(wr);
        ulonglong2 wa1 = __ldg(wr + 32);
        ulonglong2 wb0 = __ldg(wr + 64);
        ulonglong2 wb1 = __ldg(wr + 96);
#pragma unroll
        for (int q = 0; q < 4; q++) {
            const ulonglong2* up =
                reinterpret_cast<const ulonglong2*>(&u2[(g * 4 + q) * KEPI + 4 * kk]);
            ulonglong2 p0 = up[0];
            ulonglong2 p1 = up[1];
            acc[q][0] = f2fma(wa0.x, p0.x, acc[q][0]);
            acc[q][1] = f2fma(wb0.x, p0.x, acc[q][1]);
            acc[q][0] = f2fma(wa0.y, p0.y, acc[q][0]);
            acc[q][1] = f2fma(wb0.y, p0.y, acc[q][1]);
            acc[q][0] = f2fma(wa1.x, p1.x, acc[q][0]);
            acc[q][1] = f2fma(wb1.x, p1.x, acc[q][1]);
            acc[q][0] = f2fma(wa1.y, p1.y, acc[q][0]);
            acc[q][1] = f2fma(wb1.y, p1.y, acc[q][1]);
        }
    }

    float bc0 = g_bias[2 * cg];
    float bc1 = g_bias[2 * cg + 1];
#pragma unroll
    for (int q = 0; q < 4; q++) {
        float2 a0 = up2(acc[q][0]);
        float2 a1 = up2(acc[q][1]);
        int p  = g * 4 + q;
        int n0 = base + p;
        int n1 = n0 + 16;
        if (n0 < Nn) {
            float2 av = *reinterpret_cast<const float2*>(g_acc + (size_t)n0 * DD + 2 * cg);
            float2 o  = make_float2(fmaxf(a0.x + av.x + bc0, 0.f),
                                    fmaxf(a1.x + av.y + bc1, 0.f));
            *reinterpret_cast<float2*>(out + (size_t)n0 * DD + 2 * cg) = o;
        }
        if (n1 < Nn) {
            float2 av = *reinterpret_cast<const float2*>(g_acc + (size_t)n1 * DD + 2 * cg);
            float2 o  = make_float2(fmaxf(a0.y + av.x + bc0, 0.f),
                                    fmaxf(a1.y + av.y + bc1, 0.f));
            *reinterpret_cast<float2*>(out + (size_t)n1 * DD + 2 * cg) = o;
        }
    }
}

// ---------------------------------------------------------------------------
extern "C" void kernel_launch(void* const* d_in, const int* in_sizes, int n_in,
                              void* d_out, int out_size) {
    const float* x      = (const float*)d_in[0];
    const int*   elist  = (const int*)  d_in[1];
    const float* ew     = (const float*)d_in[2];
    const float* ef     = (const float*)d_in[3];
    const float* W_lin  = (const float*)d_in[4];
    const float* b_lin  = (const float*)d_in[5];
    const float* W_self = (const float*)d_in[6];
    const float* b_self = (const float*)d_in[7];
    const float* W_edge = (const float*)d_in[8];
    const float* b_edge = (const float*)d_in[9];
    float*       out    = (float*)d_out;

    int E = in_sizes[2];
    int N = in_sizes[0] / DD;

    prep_kernel<<<128, 256>>>(W_lin, b_lin, W_self, b_self, W_edge, b_edge);

    {
        int total = NN * DD / 4 + NN * RR * EDIM / 4 + NN * RR / 4;
        zero_kernel<<<(total + 255) / 256, 256>>>();
    }

    {
        dim3 grid((N + 31) / 32, RR);
        xw_kernel<<<grid, 128>>>(x, N);
    }

    edge_kernel<<<(E + 15) / 16, 256>>>(elist, ew, ef, E);

    out2_kernel<<<(N + 31) / 32, 128>>>(x, out, N);
}

// round 17
// speedup vs baseline: 2.3256x; 1.2779x over previous
#include <cuda_runtime.h>
#include <cuda_fp16.h>
#include <cstdint>

#define NN    100000
#define RR    7
#define DD    64
#define EDIM  16
#define KLIN  448              // R*D
#define KEPI  192              // 112 (F) + 16 (s + pad) + 64 (x)

typedef unsigned long long ull;

// Scratch
__device__ __half g_XWh[(size_t)NN * KLIN];    // 89.6 MB (fits L2): XW[n][r*64+c] fp16
__device__ float g_acc[(size_t)NN * DD];       // 25.6 MB (L2-resident atomics)
__device__ float g_F[(size_t)NN * RR * EDIM];  // 44.8 MB
__device__ float g_s[NN * RR];                 // 2.8 MB
__device__ ull   g_WE2[48 * 4 * 32 * 2];       // 98 KB epilogue weights (f32x2-dup, chunked)
__device__ float g_bias[DD];

// ---- f32x2 helpers --------------------------------------------------------
__device__ __forceinline__ ull f2fma(ull a, ull b, ull c) {
    ull d; asm("fma.rn.f32x2 %0, %1, %2, %3;" : "=l"(d) : "l"(a), "l"(b), "l"(c)); return d;
}
__device__ __forceinline__ float2 up2(ull v) {
    float2 r; asm("mov.b64 {%0, %1}, %2;" : "=f"(r.x), "=f"(r.y) : "l"(v)); return r;
}
__device__ __forceinline__ ull dup2(float v) {
    float2 t = make_float2(v, v);
    return *reinterpret_cast<ull*>(&t);
}

__device__ __forceinline__ uint32_t smem_u32(const void* p) {
    uint32_t a;
    asm("{ .reg .u64 t; cvta.to.shared.u64 t, %1; cvt.u32.u64 %0, t; }" : "=r"(a) : "l"(p));
    return a;
}
#define SW128(o) ((o) ^ (((o) >> 3) & 0x70))

// ---------------------------------------------------------------------------
// K0: build epilogue weights + bias
// ---------------------------------------------------------------------------
__global__ void prep_kernel(const float* __restrict__ W_lin,  const float* __restrict__ b_lin,
                            const float* __restrict__ W_self, const float* __restrict__ b_self,
                            const float* __restrict__ W_edge, const float* __restrict__ b_edge) {
    int tid    = blockIdx.x * blockDim.x + threadIdx.x;
    int stride = gridDim.x * blockDim.x;

    for (int idx = tid; idx < 48 * 4 * 32 * 2; idx += stride) {
        int j  = idx & 1;
        int cg = (idx >> 1) & 31;
        int ch = (idx >> 6) & 3;
        int kk = idx >> 8;
        int col = 2 * cg + (ch >> 1);
        int k   = 4 * kk + (ch & 1) * 2 + j;
        float v;
        if (k < 112) {              // B_r[jj][col]
            int r  = k >> 4;
            int jj = k & 15;
            float s = 0.f;
#pragma unroll 8
            for (int din = 0; din < DD; din++)
                s += W_edge[din * EDIM + jj] * W_lin[col * KLIN + r * DD + din];
            v = s;
        } else if (k < 119) {       // c_r[col]
            int r = k - 112;
            float s = 0.f;
#pragma unroll 8
            for (int din = 0; din < DD; din++)
                s += b_edge[din] * W_lin[col * KLIN + r * DD + din];
            v = s;
        } else if (k < 128) {
            v = 0.f;
        } else {
            v = W_self[col * DD + (k - 128)];
        }
        g_WE2[idx] = dup2(v);
    }
    if (tid < DD) g_bias[tid] = b_lin[tid] + b_self[tid];
}

// ---------------------------------------------------------------------------
// K1: zero g_acc + g_F + g_s
// ---------------------------------------------------------------------------
__global__ void zero_kernel() {
    const int n_acc = NN * DD / 4;
    const int n_F   = NN * RR * EDIM / 4;
    const int n_s   = NN * RR / 4;
    int i = blockIdx.x * blockDim.x + threadIdx.x;
    float4 z = make_float4(0.f, 0.f, 0.f, 0.f);
    if (i < n_acc) { reinterpret_cast<float4*>(g_acc)[i] = z; return; }
    i -= n_acc;
    if (i < n_F)   { reinterpret_cast<float4*>(g_F)[i] = z; return; }
    i -= n_F;
    if (i < n_s)   { reinterpret_cast<float4*>(g_s)[i] = z; }
}

// ---------------------------------------------------------------------------
// K2: XW via mma.sync (HMMA, baseline PTX — compiles for sm_103).
//     Grid (ceil(N/64), 7). Block 128 = 4 warps. CTA: 64 nodes x one r-slice.
//     A = x tile [64x64] fp16 SW128; B = W_lin slice [64 cols x 64 k] fp16 SW128.
//     Warp w: rows 16w..16w+15, all 64 cols: 4 k-steps x 8 n-tiles of
//     mma.m16n8k16.f32.f16.f16.f32, operands via swizzled ldmatrix.
// ---------------------------------------------------------------------------
__global__ __launch_bounds__(128) void xw_mma_kernel(const float* __restrict__ x,
                                                     const float* __restrict__ W_lin,
                                                     int Nn) {
    __shared__ __align__(128) __half smA[64 * 64];   // 8 KB
    __shared__ __align__(128) __half smB[64 * 64];   // 8 KB
    int tid   = threadIdx.x;
    int nbase = blockIdx.x * 64;
    int r     = blockIdx.y;

    // ---- stage A: 64 rows x 8 chunks of 8 halves ----
    for (int i = tid; i < 512; i += 128) {
        int row = i >> 3, ck = i & 7;
        int n = nbase + row;
        __half2 h[4];
        if (n < Nn) {
            const float4* xp = reinterpret_cast<const float4*>(x + (size_t)n * DD + ck * 8);
            float4 v0 = xp[0], v1 = xp[1];
            h[0] = __floats2half2_rn(v0.x, v0.y);
            h[1] = __floats2half2_rn(v0.z, v0.w);
            h[2] = __floats2half2_rn(v1.x, v1.y);
            h[3] = __floats2half2_rn(v1.z, v1.w);
        } else {
            h[0] = h[1] = h[2] = h[3] = __float2half2_rn(0.f);
        }
        uint32_t off = SW128((uint32_t)(row * 128 + ck * 16));
        *reinterpret_cast<uint4*>(reinterpret_cast<char*>(smA) + off) =
            *reinterpret_cast<uint4*>(h);
    }
    // ---- stage B: 64 cols x 8 chunks ----
    for (int i = tid; i < 512; i += 128) {
        int c = i >> 3, ck = i & 7;
        const float4* wp = reinterpret_cast<const float4*>(
            W_lin + (size_t)c * KLIN + r * DD + ck * 8);
        float4 v0 = wp[0], v1 = wp[1];
        __half2 h[4];
        h[0] = __floats2half2_rn(v0.x, v0.y);
        h[1] = __floats2half2_rn(v0.z, v0.w);
        h[2] = __floats2half2_rn(v1.x, v1.y);
        h[3] = __floats2half2_rn(v1.z, v1.w);
        uint32_t off = SW128((uint32_t)(c * 128 + ck * 16));
        *reinterpret_cast<uint4*>(reinterpret_cast<char*>(smB) + off) =
            *reinterpret_cast<uint4*>(h);
    }
    __syncthreads();

    int w = tid >> 5, l = tid & 31;
    uint32_t aBase = smem_u32(smA), bBase = smem_u32(smB);

    float acc[8][4];
#pragma unroll
    for (int nt = 0; nt < 8; nt++)
#pragma unroll
        for (int q = 0; q < 4; q++) acc[nt][q] = 0.f;

#pragma unroll
    for (int ks = 0; ks < 4; ks++) {
        // A fragment (m16k16): lanes 0-7 rows 0-7/k-lo, 8-15 rows 8-15/k-lo,
        //                      16-23 rows 0-7/k-hi, 24-31 rows 8-15/k-hi
        uint32_t arow   = 16 * w + (l & 15);
        uint32_t achunk = ks * 2 + (l >> 4);
        uint32_t aaddr  = aBase + SW128(arow * 128 + achunk * 16);
        uint32_t a0, a1, a2, a3;
        asm volatile("ldmatrix.sync.aligned.m8n8.x4.shared.b16 {%0,%1,%2,%3}, [%4];"
                     : "=r"(a0), "=r"(a1), "=r"(a2), "=r"(a3) : "r"(aaddr));
#pragma unroll
        for (int nt = 0; nt < 8; nt++) {
            // B fragment (k16n8, col): lanes 0-7 n-rows/k-lo, 8-15 n-rows/k-hi
            uint32_t brow   = nt * 8 + (l & 7);
            uint32_t bchunk = ks * 2 + ((l >> 3) & 1);
            uint32_t baddr  = bBase + SW128(brow * 128 + bchunk * 16);
            uint32_t b0, b1;
            asm volatile("ldmatrix.sync.aligned.m8n8.x2.shared.b16 {%0,%1}, [%2];"
                         : "=r"(b0), "=r"(b1) : "r"(baddr));
            asm volatile(
                "mma.sync.aligned.m16n8k16.row.col.f32.f16.f16.f32 "
                "{%0,%1,%2,%3}, {%4,%5,%6,%7}, {%8,%9}, {%0,%1,%2,%3};"
                : "+f"(acc[nt][0]), "+f"(acc[nt][1]), "+f"(acc[nt][2]), "+f"(acc[nt][3])
                : "r"(a0), "r"(a1), "r"(a2), "r"(a3), "r"(b0), "r"(b1));
        }
    }

    // ---- store fp16: thread l holds rows (t/4, t/4+8), cols 2(l&3),+1 per tile ----
    int row0 = nbase + 16 * w + (l >> 2);
    int row1 = row0 + 8;
#pragma unroll
    for (int nt = 0; nt < 8; nt++) {
        int colbase = r * DD + nt * 8 + 2 * (l & 3);
        if (row0 < Nn)
            *reinterpret_cast<__half2*>(g_XWh + (size_t)row0 * KLIN + colbase) =
                __floats2half2_rn(acc[nt][0], acc[nt][1]);
        if (row1 < Nn)
            *reinterpret_cast<__half2*>(g_XWh + (size_t)row1 * KLIN + colbase) =
                __floats2half2_rn(acc[nt][2], acc[nt][3]);
    }
}

// ---------------------------------------------------------------------------
// K3: edge scatter — 16 threads/edge, thread t owns [4t,4t+4).
// ---------------------------------------------------------------------------
__global__ __launch_bounds__(256) void edge_kernel(
        const int*   __restrict__ edge_list,
        const float* __restrict__ ew,
        const float* __restrict__ ef,
        int E) {
    int tid = threadIdx.x;
    int e = blockIdx.x * 16 + (tid >> 4);
    int t = tid & 15;
    if (e >= E) return;

    int ni  = edge_list[3 * e + 0];
    int no  = edge_list[3 * e + 1];
    int rel = edge_list[3 * e + 2];
    float w = ew[e];

    uint2 hraw = __ldg(reinterpret_cast<const uint2*>(
        g_XWh + (size_t)ni * KLIN + rel * DD + 4 * t));
    __half2 h0 = *reinterpret_cast<__half2*>(&hraw.x);
    __half2 h1 = *reinterpret_cast<__half2*>(&hraw.y);
    float2 f0 = __half22float2(h0);
    float2 f1 = __half22float2(h1);

    float4 val = make_float4(w * f0.x, w * f0.y, w * f1.x, w * f1.y);
    atomicAdd(reinterpret_cast<float4*>(g_acc + (size_t)no * DD + 4 * t), val);

    if (t < 4) {
        float4 fe = __ldg(reinterpret_cast<const float4*>(ef + (size_t)e * EDIM) + t);
        float4 fv = make_float4(w * fe.x, w * fe.y, w * fe.z, w * fe.w);
        atomicAdd(reinterpret_cast<float4*>(g_F + ((size_t)no * RR + rel) * EDIM + 4 * t), fv);
    }
    if (t == 0) atomicAdd(&g_s[no * RR + rel], w);
}

// ---------------------------------------------------------------------------
// K4: epilogue GEMM (K=192) over [F(112) ‖ s(7)+pad ‖ x(64)]:
//     out[n] = relu( Wfull @ in + g_acc[n] + bias )
// ---------------------------------------------------------------------------
__global__ __launch_bounds__(128) void out2_kernel(const float* __restrict__ x,
                                                   float* __restrict__ out, int Nn) {
    __shared__ __align__(16) ull u2[16 * KEPI];   // 24 KB
    int tid  = threadIdx.x;
    int base = blockIdx.x * 32;

    for (int it = 0; it < 24; it++) {
        int idx = it * 128 + tid;
        int p   = idx / KEPI;
        int k   = idx % KEPI;
        int na  = base + p, nb = na + 16;
        float a = 0.f, b = 0.f;
        if (k < 112) {
            if (na < Nn) a = g_F[(size_t)na * 112 + k];
            if (nb < Nn) b = g_F[(size_t)nb * 112 + k];
        } else if (k < 119) {
            int r = k - 112;
            if (na < Nn) a = g_s[na * RR + r];
            if (nb < Nn) b = g_s[nb * RR + r];
        } else if (k >= 128) {
            int kx = k - 128;
            if (na < Nn) a = x[(size_t)na * DD + kx];
            if (nb < Nn) b = x[(size_t)nb * DD + kx];
        }
        float2 v = make_float2(a, b);
        u2[idx] = *reinterpret_cast<ull*>(&v);
    }
    __syncthreads();

    int cg = tid & 31;
    int g  = tid >> 5;

    ull acc[4][2];
#pragma unroll
    for (int q = 0; q < 4; q++) { acc[q][0] = 0ull; acc[q][1] = 0ull; }

#pragma unroll 2
    for (int kk = 0; kk < 48; kk++) {
        const ulonglong2* wr = reinterpret_cast<const ulonglong2*>(g_WE2) + kk * 128 + cg;
        ulonglong2 wa0 = __ldg(wr);
        ulonglong2 wa1 = __ldg(wr + 32);
        ulonglong2 wb0 = __ldg(wr + 64);
        ulonglong2 wb1 = __ldg(wr + 96);
#pragma unroll
        for (int q = 0; q < 4; q++) {
            const ulonglong2* up =
                reinterpret_cast<const ulonglong2*>(&u2[(g * 4 + q) * KEPI + 4 * kk]);
            ulonglong2 p0 = up[0];
            ulonglong2 p1 = up[1];
            acc[q][0] = f2fma(wa0.x, p0.x, acc[q][0]);
            acc[q][1] = f2fma(wb0.x, p0.x, acc[q][1]);
            acc[q][0] = f2fma(wa0.y, p0.y, acc[q][0]);
            acc[q][1] = f2fma(wb0.y, p0.y, acc[q][1]);
            acc[q][0] = f2fma(wa1.x, p1.x, acc[q][0]);
            acc[q][1] = f2fma(wb1.x, p1.x, acc[q][1]);
            acc[q][0] = f2fma(wa1.y, p1.y, acc[q][0]);
            acc[q][1] = f2fma(wb1.y, p1.y, acc[q][1]);
        }
    }

    float bc0 = g_bias[2 * cg];
    float bc1 = g_bias[2 * cg + 1];
#pragma unroll
    for (int q = 0; q < 4; q++) {
        float2 a0 = up2(acc[q][0]);
        float2 a1 = up2(acc[q][1]);
        int p  = g * 4 + q;
        int n0 = base + p;
        int n1 = n0 + 16;
        if (n0 < Nn) {
            float2 av = *reinterpret_cast<const float2*>(g_acc + (size_t)n0 * DD + 2 * cg);
            float2 o  = make_float2(fmaxf(a0.x + av.x + bc0, 0.f),
                                    fmaxf(a1.x + av.y + bc1, 0.f));
            *reinterpret_cast<float2*>(out + (size_t)n0 * DD + 2 * cg) = o;
        }
        if (n1 < Nn) {
            float2 av = *reinterpret_cast<const float2*>(g_acc + (size_t)n1 * DD + 2 * cg);
            float2 o  = make_float2(fmaxf(a0.y + av.x + bc0, 0.f),
                                    fmaxf(a1.y + av.y + bc1, 0.f));
            *reinterpret_cast<float2*>(out + (size_t)n1 * DD + 2 * cg) = o;
        }
    }
}

// ---------------------------------------------------------------------------
extern "C" void kernel_launch(void* const* d_in, const int* in_sizes, int n_in,
                              void* d_out, int out_size) {
    const float* x      = (const float*)d_in[0];
    const int*   elist  = (const int*)  d_in[1];
    const float* ew     = (const float*)d_in[2];
    const float* ef     = (const float*)d_in[3];
    const float* W_lin  = (const float*)d_in[4];
    const float* b_lin  = (const float*)d_in[5];
    const float* W_self = (const float*)d_in[6];
    const float* b_self = (const float*)d_in[7];
    const float* W_edge = (const float*)d_in[8];
    const float* b_edge = (const float*)d_in[9];
    float*       out    = (float*)d_out;

    int E = in_sizes[2];
    int N = in_sizes[0] / DD;

    prep_kernel<<<128, 256>>>(W_lin, b_lin, W_self, b_self, W_edge, b_edge);

    {
        int total = NN * DD / 4 + NN * RR * EDIM / 4 + NN * RR / 4;
        zero_kernel<<<(total + 255) / 256, 256>>>();
    }

    {
        dim3 grid((N + 63) / 64, RR);
        xw_mma_kernel<<<grid, 128>>>(x, W_lin, N);
    }

    edge_kernel<<<(E + 15) / 16, 256>>>(elist, ew, ef, E);

    out2_kernel<<<(N + 31) / 32, 128>>>(x, out, N);
}